// round 16
// baseline (speedup 1.0000x reference)
#include <cuda_runtime.h>
#include <cstdint>

#define NB 65536
#define NT 12
#define HD 128
#define G3 384
#define ROWS 64
#define NTHR 512
#define APAD 132                      // f32 tile row stride (floats)
#define APADH 136                     // fp16 tile row stride (halves)
#define TSZ (ROWS * APAD)             // floats per f32 tile
#define HTSZ (ROWS * APADH)           // halves per fp16 tile
// SMEM: he0,he1,he2 exact f32 + rh0,rh1,rh2,rxe fp16
#define SMEM_NET (3 * TSZ * 4 + 4 * HTSZ * 2)   // 171008 B

// ---- device scratch (no allocation allowed) ----
// Pre-packed fp16 GRU weights. Per cell: 6 jobs [r_x, r_h, z_x, z_h, n_x, n_h].
// Job = 8 kt16 x 8 n-pairs; pair-block = 128 uint32: lane*4 + {b0e,b1e,b0o,b1o}.
__device__ __align__(16) float g_wB[6][6 * 8192];
// Dense weights in identical job format: [0]=enc_Wt, [1]=dec_Win
__device__ __align__(16) float g_wD[2][8192];

// ================= helpers =================
__device__ __forceinline__ uint32_t smem_u32(const void* p) {
    uint32_t a;
    asm("{ .reg .u64 t; cvta.to.shared.u64 t, %1; cvt.u32.u64 %0, t; }" : "=r"(a) : "l"(p));
    return a;
}
__device__ __forceinline__ uint32_t f16x2(float lo, float hi) {
    uint32_t r; asm("cvt.rn.f16x2.f32 %0, %1, %2;" : "=r"(r) : "f"(hi), "f"(lo));
    return r;
}
__device__ __forceinline__ float sigmoid_f(float x) {
    return __fdividef(1.0f, 1.0f + __expf(-x));
}
__device__ __forceinline__ float tanh_f(float x) {
    x = fminf(fmaxf(x, -9.0f), 9.0f);
    float e = __expf(2.0f * x);
    return __fdividef(e - 1.0f, e + 1.0f);
}
__device__ __forceinline__ float2 lds2(uint32_t a) {
    float2 v; asm volatile("ld.shared.v2.f32 {%0,%1}, [%2];" : "=f"(v.x), "=f"(v.y) : "r"(a));
    return v;
}
__device__ __forceinline__ void sts2(uint32_t a, float2 v) {
    asm volatile("st.shared.v2.f32 [%0], {%1,%2};" :: "r"(a), "f"(v.x), "f"(v.y) : "memory");
}
__device__ __forceinline__ void sts1u(uint32_t a, uint32_t v) {
    asm volatile("st.shared.b32 [%0], %1;" :: "r"(a), "r"(v) : "memory");
}

#define LDSM4(r0, r1, r2, r3, addr) \
    asm volatile("ldmatrix.sync.aligned.m8n8.x4.shared.b16 {%0,%1,%2,%3}, [%4];" \
                 : "=r"(r0), "=r"(r1), "=r"(r2), "=r"(r3) : "r"(addr))

#define MMA16(acc, a, b0, b1) \
    asm volatile( \
        "mma.sync.aligned.m16n8k16.row.col.f32.f16.f16.f32 " \
        "{%0,%1,%2,%3}, {%4,%5,%6,%7}, {%8,%9}, {%0,%1,%2,%3};" \
        : "+f"((acc)[0]), "+f"((acc)[1]), "+f"((acc)[2]), "+f"((acc)[3]) \
        : "r"((a)[0]), "r"((a)[1]), "r"((a)[2]), "r"((a)[3]), "r"(b0), "r"(b1))

// ================= prep kernels =================
__global__ void k_prep_all(const float* __restrict__ eWih, const float* __restrict__ eWhh,
                           const float* __restrict__ dWih, const float* __restrict__ dWhh) {
    int wsel = blockIdx.x / 192;
    int i = (blockIdx.x % 192) * 256 + threadIdx.x;
    int l = wsel % 3;
    const float* Wih = (wsel < 3 ? eWih : dWih) + (size_t)l * G3 * HD;
    const float* Whh = (wsel < 3 ? eWhh : dWhh) + (size_t)l * G3 * HD;
    int j  = i >> 13;
    int pi = i & 8191;
    int kt = pi >> 10;
    int p  = (pi >> 7) & 7;
    int w  = pi & 127;
    int lane = w >> 2, q = w & 3;
    const float* W = (j & 1) ? Whh : Wih;
    int gbase = (j >> 1) * 128;
    int n = (p * 2 + (q >> 1)) * 8 + (lane >> 2);
    int k = kt * 16 + (lane & 3) * 2 + (q & 1) * 8;
    const float* src = W + (size_t)(gbase + n) * HD + k;
    reinterpret_cast<uint32_t*>(g_wB[wsel])[j * 8192 + (kt * 8 + p) * 128 + lane * 4 + q] =
        f16x2(src[0], src[1]);
}

__global__ void k_prep_dense(const float* __restrict__ enc_Wt,
                             const float* __restrict__ dec_Win) {
    int i = blockIdx.x * 256 + threadIdx.x;   // 16384
    int sel = i >> 13;
    int pi = i & 8191;
    int kt = pi >> 10;
    int p  = (pi >> 7) & 7;
    int w  = pi & 127;
    int lane = w >> 2, q = w & 3;
    const float* W = sel ? dec_Win : enc_Wt;
    int n = (p * 2 + (q >> 1)) * 8 + (lane >> 2);
    int k = kt * 16 + (lane & 3) * 2 + (q & 1) * 8;
    const float* src = W + (size_t)n * HD + k;
    reinterpret_cast<uint32_t*>(g_wD[sel])[(kt * 8 + p) * 128 + lane * 4 + q] =
        f16x2(src[0], src[1]);
}

// ================= fused GRU cell (SMEM-resident, fp16 mma) =================
// 64 rows; 16 warps: 2(m) x 8(n); warp tile 32(m) x 16(n), k16 steps.
// Per-output accumulation order identical to R13 -> bit-identical results.
__device__ __noinline__ void cellf(uint32_t rx, uint32_t hsrc, uint32_t he,
                                   const float* __restrict__ WB,
                                   const float* __restrict__ bih,
                                   const float* __restrict__ bhh,
                                   uint32_t rhOut) {
    const int tid = threadIdx.x, wid = tid >> 5, lane = tid & 31;
    const int warpm = wid >> 3, warpn = wid & 7;
    const int g = lane >> 2, t4 = lane & 3;
    const int f = lane >> 3, r8 = lane & 7;
    const uint32_t lmoff = (uint32_t)(warpm * 32 + r8) * (APADH * 2)
                         + ((f & 1) ? 8 * APADH * 2 : 0u) + ((f >> 1) ? 16u : 0u);

    float aR[2][2][4], aZ[2][2][4], aNX[2][2][4], aNH[2][2][4];
    #pragma unroll
    for (int m = 0; m < 2; m++)
        #pragma unroll
        for (int n = 0; n < 2; n++)
            #pragma unroll
            for (int e = 0; e < 4; e++) {
                aR[m][n][e] = 0.0f; aZ[m][n][e] = 0.0f;
                aNX[m][n][e] = 0.0f; aNH[m][n][e] = 0.0f;
            }

    auto sweep = [&](uint32_t As, const float* __restrict__ B0,
                     const float* __restrict__ B1, const float* __restrict__ B2,
                     float (&c0)[2][2][4], float (&c1)[2][2][4], float (&c2)[2][2][4]) {
        #pragma unroll 2
        for (int kt = 0; kt < 8; kt++) {
            uint32_t A0 = As + lmoff + kt * 32;
            uint32_t a[2][4];
            LDSM4(a[0][0], a[0][1], a[0][2], a[0][3], A0);
            LDSM4(a[1][0], a[1][1], a[1][2], a[1][3], A0 + 16 * APADH * 2);
            const int fo = (kt * 8 + warpn) * 128 + lane * 4;
            float4 bv;
            bv = *reinterpret_cast<const float4*>(B0 + fo);
            MMA16(c0[0][0], a[0], __float_as_uint(bv.x), __float_as_uint(bv.y));
            MMA16(c0[0][1], a[0], __float_as_uint(bv.z), __float_as_uint(bv.w));
            MMA16(c0[1][0], a[1], __float_as_uint(bv.x), __float_as_uint(bv.y));
            MMA16(c0[1][1], a[1], __float_as_uint(bv.z), __float_as_uint(bv.w));
            bv = *reinterpret_cast<const float4*>(B1 + fo);
            MMA16(c1[0][0], a[0], __float_as_uint(bv.x), __float_as_uint(bv.y));
            MMA16(c1[0][1], a[0], __float_as_uint(bv.z), __float_as_uint(bv.w));
            MMA16(c1[1][0], a[1], __float_as_uint(bv.x), __float_as_uint(bv.y));
            MMA16(c1[1][1], a[1], __float_as_uint(bv.z), __float_as_uint(bv.w));
            bv = *reinterpret_cast<const float4*>(B2 + fo);
            MMA16(c2[0][0], a[0], __float_as_uint(bv.x), __float_as_uint(bv.y));
            MMA16(c2[0][1], a[0], __float_as_uint(bv.z), __float_as_uint(bv.w));
            MMA16(c2[1][0], a[1], __float_as_uint(bv.x), __float_as_uint(bv.y));
            MMA16(c2[1][1], a[1], __float_as_uint(bv.z), __float_as_uint(bv.w));
        }
    };

    sweep(rx,   WB,            WB + 2 * 8192, WB + 4 * 8192, aR, aZ, aNX);  // x: r,z,nx
    sweep(hsrc, WB + 1 * 8192, WB + 3 * 8192, WB + 5 * 8192, aR, aZ, aNH);  // h: r,z,nh

    __syncthreads();    // all sweep reads of h tiles done before in-place update
    #pragma unroll
    for (int mt = 0; mt < 2; mt++)
        #pragma unroll
        for (int nt = 0; nt < 2; nt++) {
            int col = warpn * 16 + nt * 8 + t4 * 2;
            float br0 = bih[col] + bhh[col],             br1 = bih[col + 1] + bhh[col + 1];
            float bz0 = bih[128 + col] + bhh[128 + col], bz1 = bih[129 + col] + bhh[129 + col];
            float bnx0 = bih[256 + col], bnx1 = bih[257 + col];
            float bnh0 = bhh[256 + col], bnh1 = bhh[257 + col];
            uint32_t off = ((uint32_t)(warpm * 32 + mt * 16 + g) * APAD + col) * 4;
            uint32_t h0a = he + off, h1a = h0a + 8 * APAD * 4;
            float2 ho0 = lds2(h0a), ho1 = lds2(h1a);

            float r0v = sigmoid_f(aR[mt][nt][0] + br0);
            float r1v = sigmoid_f(aR[mt][nt][1] + br1);
            float r2v = sigmoid_f(aR[mt][nt][2] + br0);
            float r3v = sigmoid_f(aR[mt][nt][3] + br1);
            float z0 = sigmoid_f(aZ[mt][nt][0] + bz0);
            float z1 = sigmoid_f(aZ[mt][nt][1] + bz1);
            float z2 = sigmoid_f(aZ[mt][nt][2] + bz0);
            float z3 = sigmoid_f(aZ[mt][nt][3] + bz1);
            float n0 = tanh_f(aNX[mt][nt][0] + bnx0 + r0v * (aNH[mt][nt][0] + bnh0));
            float n1 = tanh_f(aNX[mt][nt][1] + bnx1 + r1v * (aNH[mt][nt][1] + bnh1));
            float n2 = tanh_f(aNX[mt][nt][2] + bnx0 + r2v * (aNH[mt][nt][2] + bnh0));
            float n3 = tanh_f(aNX[mt][nt][3] + bnx1 + r3v * (aNH[mt][nt][3] + bnh1));
            float2 o0, o1;
            o0.x = fmaf(z0, ho0.x - n0, n0);
            o0.y = fmaf(z1, ho0.y - n1, n1);
            o1.x = fmaf(z2, ho1.x - n2, n2);
            o1.y = fmaf(z3, ho1.y - n3, n3);
            sts2(h0a, o0);
            sts2(h1a, o1);
            uint32_t offh = ((uint32_t)(warpm * 32 + mt * 16 + g) * APADH + col) * 2;
            sts1u(rhOut + offh, f16x2(o0.x, o0.y));
            sts1u(rhOut + offh + 8 * APADH * 2, f16x2(o1.x, o1.y));
        }
    __syncthreads();
}

// ================= fp16-mma 128x128 dense, SMEM(fp16)->SMEM(fp16) =================
__device__ __noinline__ void dense16(uint32_t src, uint32_t dst,
                                     const float* __restrict__ WJ,
                                     const float* __restrict__ bias, int relu) {
    const int tid = threadIdx.x, wid = tid >> 5, lane = tid & 31;
    const int warpm = wid >> 3, warpn = wid & 7;
    const int g = lane >> 2, t4 = lane & 3;
    const int f = lane >> 3, r8 = lane & 7;
    const uint32_t lmoff = (uint32_t)(warpm * 32 + r8) * (APADH * 2)
                         + ((f & 1) ? 8 * APADH * 2 : 0u) + ((f >> 1) ? 16u : 0u);
    float acc[2][2][4];
    #pragma unroll
    for (int m = 0; m < 2; m++)
        #pragma unroll
        for (int n = 0; n < 2; n++)
            #pragma unroll
            for (int e = 0; e < 4; e++) acc[m][n][e] = 0.0f;

    #pragma unroll 2
    for (int kt = 0; kt < 8; kt++) {
        uint32_t A0 = src + lmoff + kt * 32;
        uint32_t a[2][4];
        LDSM4(a[0][0], a[0][1], a[0][2], a[0][3], A0);
        LDSM4(a[1][0], a[1][1], a[1][2], a[1][3], A0 + 16 * APADH * 2);
        float4 bv = *reinterpret_cast<const float4*>(WJ + (kt * 8 + warpn) * 128 + lane * 4);
        MMA16(acc[0][0], a[0], __float_as_uint(bv.x), __float_as_uint(bv.y));
        MMA16(acc[0][1], a[0], __float_as_uint(bv.z), __float_as_uint(bv.w));
        MMA16(acc[1][0], a[1], __float_as_uint(bv.x), __float_as_uint(bv.y));
        MMA16(acc[1][1], a[1], __float_as_uint(bv.z), __float_as_uint(bv.w));
    }
    #pragma unroll
    for (int mt = 0; mt < 2; mt++)
        #pragma unroll
        for (int nt = 0; nt < 2; nt++) {
            int col = warpn * 16 + nt * 8 + t4 * 2;
            float b0 = bias[col], b1 = bias[col + 1];
            float v0 = acc[mt][nt][0] + b0, v1 = acc[mt][nt][1] + b1;
            float v2 = acc[mt][nt][2] + b0, v3 = acc[mt][nt][3] + b1;
            if (relu) {
                v0 = fmaxf(v0, 0.0f); v1 = fmaxf(v1, 0.0f);
                v2 = fmaxf(v2, 0.0f); v3 = fmaxf(v3, 0.0f);
            }
            uint32_t offh = ((uint32_t)(warpm * 32 + mt * 16 + g) * APADH + col) * 2;
            sts1u(dst + offh, f16x2(v0, v1));
            sts1u(dst + offh + 8 * APADH * 2, f16x2(v2, v3));
        }
    __syncthreads();
}

// ================= fused whole-network kernel =================
__global__ void __launch_bounds__(NTHR, 1)
k_net(const float* __restrict__ x_true, float* __restrict__ out,
      const float* __restrict__ Wemb, const float* __restrict__ bemb,
      const float* __restrict__ enc_bih, const float* __restrict__ enc_bhh,
      const float* __restrict__ enc_bt, const float* __restrict__ dec_bin,
      const float* __restrict__ dec_bih, const float* __restrict__ dec_bhh,
      const float* __restrict__ Wout, const float* __restrict__ bout) {
    extern __shared__ float sm[];
    const uint32_t sb = smem_u32(sm);
    const uint32_t he0 = sb, he1 = sb + TSZ * 4, he2 = sb + 2 * TSZ * 4;
    const uint32_t h16 = sb + 3 * TSZ * 4;
    const uint32_t rh0 = h16, rh1 = h16 + HTSZ * 2, rh2 = h16 + 2 * HTSZ * 2;
    const uint32_t rxe = h16 + 3 * HTSZ * 2;
    const int tid = threadIdx.x;
    const int row0 = blockIdx.x * ROWS;
    const int NFLT = 3 * TSZ + 2 * HTSZ;            // total smem floats

    for (int i = tid; i < NFLT; i += NTHR) sm[i] = 0.0f;
    __syncthreads();

    // ---- encoder: steps t = 1..T-2 (step 0 discarded per reference) ----
    #pragma unroll 1
    for (int t = 1; t <= NT - 2; t++) {
        #pragma unroll 1
        for (int i = tid; i < ROWS * 64; i += NTHR) {
            int r = i >> 6, c = (i & 63) * 2;
            float2 xp = *reinterpret_cast<const float2*>(
                x_true + ((size_t)(row0 + r) * NT + t) * 2);
            float v0 = fmaxf(fmaf(xp.x, Wemb[2 * c],
                                  fmaf(xp.y, Wemb[2 * c + 1], bemb[c])), 0.0f);
            float v1 = fmaxf(fmaf(xp.x, Wemb[2 * c + 2],
                                  fmaf(xp.y, Wemb[2 * c + 3], bemb[c + 1])), 0.0f);
            sts1u(rxe + ((uint32_t)r * APADH + c) * 2, f16x2(v0, v1));
        }
        __syncthreads();
        cellf(rxe, rh0, he0, g_wB[0], enc_bih,          enc_bhh,          rh0);
        cellf(rh0, rh1, he1, g_wB[1], enc_bih + G3,     enc_bhh + G3,     rh1);
        cellf(rh1, rh2, he2, g_wB[2], enc_bih + 2 * G3, enc_bhh + 2 * G3, rh2);
    }

    // rep = h_top @ enc_Wt^T + bt (fp16, no relu) -> rh0 (enc layer-0 h is dead)
    dense16(rh2, rh0, g_wD[0], enc_bt, 0);
    // decoder step-0 input projection: relu(rep @ Win^T + bin) -> rxe
    dense16(rh0, rxe, g_wD[1], dec_bin, 1);

    // zero ALL h tiles (f32 he0..he2 + fp16 rh0..rh2); keep rxe
    for (int i = tid; i < 3 * TSZ + 3 * HTSZ / 2; i += NTHR) sm[i] = 0.0f;
    __syncthreads();

    // ---- decoder: 12 steps; carry = top hidden ----
    #pragma unroll 1
    for (int i = 0; i < NT; i++) {
        if (i) dense16(rh2, rxe, g_wD[1], dec_bin, 1);
        cellf(rxe, rh0, he0, g_wB[3], dec_bih,          dec_bhh,          rh0);
        cellf(rh0, rh1, he1, g_wB[4], dec_bih + G3,     dec_bhh + G3,     rh1);
        cellf(rh1, rh2, he2, g_wB[5], dec_bih + 2 * G3, dec_bhh + 2 * G3, rh2);

        // output head: y = h_top @ Wout^T + bout  (exact he2)
        {
            int wid = tid >> 5, lane = tid & 31;
            float4 w0 = *reinterpret_cast<const float4*>(Wout + lane * 4);
            float4 w1 = *reinterpret_cast<const float4*>(Wout + HD + lane * 4);
            #pragma unroll
            for (int rr = 0; rr < 4; rr++) {
                int r = wid * 4 + rr;
                float4 hv = *reinterpret_cast<const float4*>(
                    sm + 2 * TSZ + r * APAD + lane * 4);
                float d0 = hv.x * w0.x + hv.y * w0.y + hv.z * w0.z + hv.w * w0.w;
                float d1 = hv.x * w1.x + hv.y * w1.y + hv.z * w1.z + hv.w * w1.w;
                #pragma unroll
                for (int s = 16; s; s >>= 1) {
                    d0 += __shfl_xor_sync(0xFFFFFFFFu, d0, s);
                    d1 += __shfl_xor_sync(0xFFFFFFFFu, d1, s);
                }
                if (lane == 0) {
                    float* o = out + ((size_t)(row0 + r) * NT + i) * 2;
                    o[0] = d0 + bout[0];
                    o[1] = d1 + bout[1];
                }
            }
        }
    }
}

extern "C" void kernel_launch(void* const* d_in, const int* in_sizes, int n_in,
                              void* d_out, int out_size) {
    const float* x_true   = (const float*)d_in[0];
    const float* enc_Wemb = (const float*)d_in[1];
    const float* enc_bemb = (const float*)d_in[2];
    const float* enc_Wih  = (const float*)d_in[3];
    const float* enc_Whh  = (const float*)d_in[4];
    const float* enc_bih  = (const float*)d_in[5];
    const float* enc_bhh  = (const float*)d_in[6];
    const float* enc_Wt   = (const float*)d_in[7];
    const float* enc_bt   = (const float*)d_in[8];
    const float* dec_Win  = (const float*)d_in[9];
    const float* dec_bin  = (const float*)d_in[10];
    const float* dec_Wih  = (const float*)d_in[11];
    const float* dec_Whh  = (const float*)d_in[12];
    const float* dec_bih  = (const float*)d_in[13];
    const float* dec_bhh  = (const float*)d_in[14];
    const float* dec_Wout = (const float*)d_in[15];
    const float* dec_bout = (const float*)d_in[16];
    float* out = (float*)d_out;

    cudaFuncSetAttribute(k_net, cudaFuncAttributeMaxDynamicSharedMemorySize, SMEM_NET);

    k_prep_all<<<6 * 192, 256>>>(enc_Wih, enc_Whh, dec_Wih, dec_Whh);
    k_prep_dense<<<64, 256>>>(enc_Wt, dec_Win);
    k_net<<<NB / ROWS, NTHR, SMEM_NET>>>(x_true, out, enc_Wemb, enc_bemb,
                                         enc_bih, enc_bhh, enc_bt, dec_bin,
                                         dec_bih, dec_bhh, dec_Wout, dec_bout);
}

// round 17
// speedup vs baseline: 1.1199x; 1.1199x over previous
#include <cuda_runtime.h>
#include <cstdint>

#define NB 65536
#define NT 12
#define HD 128
#define G3 384
#define ROWS 32
#define NTHR 256
#define APAD 132                      // f32 tile row stride (floats)
#define APADH 136                     // fp16 tile row stride (halves)
#define TSZ (ROWS * APAD)             // floats per f32 tile
#define HTSZ (ROWS * APADH)           // halves per fp16 tile
// SMEM: he0,he1,he2 exact f32 + 6 ping-pong rh fp16 + rxe fp16
#define SMEM_NET (3 * TSZ * 4 + 7 * HTSZ * 2)   // 111616 B

// ---- device scratch (no allocation allowed) ----
// Pre-packed fp16 GRU weights. Per cell: 6 jobs [r_x, r_h, z_x, z_h, n_x, n_h].
// Job = 8 kt16 x 8 n-pairs; pair-block = 128 uint32: lane*4 + {b0e,b1e,b0o,b1o}.
__device__ __align__(16) float g_wB[6][6 * 8192];
// Dense weights in identical job format: [0]=enc_Wt, [1]=dec_Win
__device__ __align__(16) float g_wD[2][8192];

// ================= helpers =================
__device__ __forceinline__ uint32_t smem_u32(const void* p) {
    uint32_t a;
    asm("{ .reg .u64 t; cvta.to.shared.u64 t, %1; cvt.u32.u64 %0, t; }" : "=r"(a) : "l"(p));
    return a;
}
__device__ __forceinline__ uint32_t f16x2(float lo, float hi) {
    uint32_t r; asm("cvt.rn.f16x2.f32 %0, %1, %2;" : "=r"(r) : "f"(hi), "f"(lo));
    return r;
}
__device__ __forceinline__ float sigmoid_f(float x) {
    return __fdividef(1.0f, 1.0f + __expf(-x));
}
__device__ __forceinline__ float tanh_f(float x) {
    x = fminf(fmaxf(x, -9.0f), 9.0f);
    float e = __expf(2.0f * x);
    return __fdividef(e - 1.0f, e + 1.0f);
}
__device__ __forceinline__ float2 lds2(uint32_t a) {
    float2 v; asm volatile("ld.shared.v2.f32 {%0,%1}, [%2];" : "=f"(v.x), "=f"(v.y) : "r"(a));
    return v;
}
__device__ __forceinline__ void sts2(uint32_t a, float2 v) {
    asm volatile("st.shared.v2.f32 [%0], {%1,%2};" :: "r"(a), "f"(v.x), "f"(v.y) : "memory");
}
__device__ __forceinline__ void sts1u(uint32_t a, uint32_t v) {
    asm volatile("st.shared.b32 [%0], %1;" :: "r"(a), "r"(v) : "memory");
}

#define LDSM4(r0, r1, r2, r3, addr) \
    asm volatile("ldmatrix.sync.aligned.m8n8.x4.shared.b16 {%0,%1,%2,%3}, [%4];" \
                 : "=r"(r0), "=r"(r1), "=r"(r2), "=r"(r3) : "r"(addr))

#define MMA16(acc, a, b0, b1) \
    asm volatile( \
        "mma.sync.aligned.m16n8k16.row.col.f32.f16.f16.f32 " \
        "{%0,%1,%2,%3}, {%4,%5,%6,%7}, {%8,%9}, {%0,%1,%2,%3};" \
        : "+f"((acc)[0]), "+f"((acc)[1]), "+f"((acc)[2]), "+f"((acc)[3]) \
        : "r"((a)[0]), "r"((a)[1]), "r"((a)[2]), "r"((a)[3]), "r"(b0), "r"(b1))

// ================= prep kernels =================
__global__ void k_prep_all(const float* __restrict__ eWih, const float* __restrict__ eWhh,
                           const float* __restrict__ dWih, const float* __restrict__ dWhh) {
    int wsel = blockIdx.x / 192;
    int i = (blockIdx.x % 192) * 256 + threadIdx.x;
    int l = wsel % 3;
    const float* Wih = (wsel < 3 ? eWih : dWih) + (size_t)l * G3 * HD;
    const float* Whh = (wsel < 3 ? eWhh : dWhh) + (size_t)l * G3 * HD;
    int j  = i >> 13;
    int pi = i & 8191;
    int kt = pi >> 10;
    int p  = (pi >> 7) & 7;
    int w  = pi & 127;
    int lane = w >> 2, q = w & 3;
    const float* W = (j & 1) ? Whh : Wih;
    int gbase = (j >> 1) * 128;
    int n = (p * 2 + (q >> 1)) * 8 + (lane >> 2);
    int k = kt * 16 + (lane & 3) * 2 + (q & 1) * 8;
    const float* src = W + (size_t)(gbase + n) * HD + k;
    reinterpret_cast<uint32_t*>(g_wB[wsel])[j * 8192 + (kt * 8 + p) * 128 + lane * 4 + q] =
        f16x2(src[0], src[1]);
}

__global__ void k_prep_dense(const float* __restrict__ enc_Wt,
                             const float* __restrict__ dec_Win) {
    int i = blockIdx.x * 256 + threadIdx.x;   // 16384
    int sel = i >> 13;
    int pi = i & 8191;
    int kt = pi >> 10;
    int p  = (pi >> 7) & 7;
    int w  = pi & 127;
    int lane = w >> 2, q = w & 3;
    const float* W = sel ? dec_Win : enc_Wt;
    int n = (p * 2 + (q >> 1)) * 8 + (lane >> 2);
    int k = kt * 16 + (lane & 3) * 2 + (q & 1) * 8;
    const float* src = W + (size_t)n * HD + k;
    reinterpret_cast<uint32_t*>(g_wD[sel])[(kt * 8 + p) * 128 + lane * 4 + q] =
        f16x2(src[0], src[1]);
}

// ================= fused GRU cell (SMEM-resident, fp16 mma) =================
// 32 rows; 8 warps all in n: warp tile 32(m) x 16(n), k16 steps.
// rhOut != hsrc (ping-pong) -> NO barrier between sweeps and epilogue:
// each warp flows into its epilogue; MUFU overlaps other warps' mma.
__device__ __noinline__ void cellf(uint32_t rx, uint32_t hsrc, uint32_t he,
                                   const float* __restrict__ WB,
                                   const float* __restrict__ bih,
                                   const float* __restrict__ bhh,
                                   uint32_t rhOut) {
    const int tid = threadIdx.x, wid = tid >> 5, lane = tid & 31;
    const int g = lane >> 2, t4 = lane & 3;
    const int f = lane >> 3, r8 = lane & 7;
    const uint32_t lmoff = (uint32_t)r8 * (APADH * 2)
                         + ((f & 1) ? 8 * APADH * 2 : 0u) + ((f >> 1) ? 16u : 0u);

    float aR[2][2][4], aZ[2][2][4], aNX[2][2][4], aNH[2][2][4];
    #pragma unroll
    for (int m = 0; m < 2; m++)
        #pragma unroll
        for (int n = 0; n < 2; n++)
            #pragma unroll
            for (int e = 0; e < 4; e++) {
                aR[m][n][e] = 0.0f; aZ[m][n][e] = 0.0f;
                aNX[m][n][e] = 0.0f; aNH[m][n][e] = 0.0f;
            }

    auto sweep = [&](uint32_t As, const float* __restrict__ B0,
                     const float* __restrict__ B1, const float* __restrict__ B2,
                     float (&c0)[2][2][4], float (&c1)[2][2][4], float (&c2)[2][2][4]) {
        #pragma unroll 2
        for (int kt = 0; kt < 8; kt++) {
            uint32_t A0 = As + lmoff + kt * 32;
            uint32_t a[2][4];
            LDSM4(a[0][0], a[0][1], a[0][2], a[0][3], A0);
            LDSM4(a[1][0], a[1][1], a[1][2], a[1][3], A0 + 16 * APADH * 2);
            const int fo = (kt * 8 + wid) * 128 + lane * 4;
            float4 bv;
            bv = *reinterpret_cast<const float4*>(B0 + fo);
            MMA16(c0[0][0], a[0], __float_as_uint(bv.x), __float_as_uint(bv.y));
            MMA16(c0[0][1], a[0], __float_as_uint(bv.z), __float_as_uint(bv.w));
            MMA16(c0[1][0], a[1], __float_as_uint(bv.x), __float_as_uint(bv.y));
            MMA16(c0[1][1], a[1], __float_as_uint(bv.z), __float_as_uint(bv.w));
            bv = *reinterpret_cast<const float4*>(B1 + fo);
            MMA16(c1[0][0], a[0], __float_as_uint(bv.x), __float_as_uint(bv.y));
            MMA16(c1[0][1], a[0], __float_as_uint(bv.z), __float_as_uint(bv.w));
            MMA16(c1[1][0], a[1], __float_as_uint(bv.x), __float_as_uint(bv.y));
            MMA16(c1[1][1], a[1], __float_as_uint(bv.z), __float_as_uint(bv.w));
            bv = *reinterpret_cast<const float4*>(B2 + fo);
            MMA16(c2[0][0], a[0], __float_as_uint(bv.x), __float_as_uint(bv.y));
            MMA16(c2[0][1], a[0], __float_as_uint(bv.z), __float_as_uint(bv.w));
            MMA16(c2[1][0], a[1], __float_as_uint(bv.x), __float_as_uint(bv.y));
            MMA16(c2[1][1], a[1], __float_as_uint(bv.z), __float_as_uint(bv.w));
        }
    };

    sweep(rx,   WB,            WB + 2 * 8192, WB + 4 * 8192, aR, aZ, aNX);  // x: r,z,nx
    sweep(hsrc, WB + 1 * 8192, WB + 3 * 8192, WB + 5 * 8192, aR, aZ, aNH);  // h: r,z,nh

    // no barrier: rhOut is the alternate buffer; he is thread-local in-place
    #pragma unroll
    for (int mt = 0; mt < 2; mt++)
        #pragma unroll
        for (int nt = 0; nt < 2; nt++) {
            int col = wid * 16 + nt * 8 + t4 * 2;
            float br0 = bih[col] + bhh[col],             br1 = bih[col + 1] + bhh[col + 1];
            float bz0 = bih[128 + col] + bhh[128 + col], bz1 = bih[129 + col] + bhh[129 + col];
            float bnx0 = bih[256 + col], bnx1 = bih[257 + col];
            float bnh0 = bhh[256 + col], bnh1 = bhh[257 + col];
            uint32_t off = ((uint32_t)(mt * 16 + g) * APAD + col) * 4;
            uint32_t h0a = he + off, h1a = h0a + 8 * APAD * 4;
            float2 ho0 = lds2(h0a), ho1 = lds2(h1a);

            float r0v = sigmoid_f(aR[mt][nt][0] + br0);
            float r1v = sigmoid_f(aR[mt][nt][1] + br1);
            float r2v = sigmoid_f(aR[mt][nt][2] + br0);
            float r3v = sigmoid_f(aR[mt][nt][3] + br1);
            float z0 = sigmoid_f(aZ[mt][nt][0] + bz0);
            float z1 = sigmoid_f(aZ[mt][nt][1] + bz1);
            float z2 = sigmoid_f(aZ[mt][nt][2] + bz0);
            float z3 = sigmoid_f(aZ[mt][nt][3] + bz1);
            float n0 = tanh_f(aNX[mt][nt][0] + bnx0 + r0v * (aNH[mt][nt][0] + bnh0));
            float n1 = tanh_f(aNX[mt][nt][1] + bnx1 + r1v * (aNH[mt][nt][1] + bnh1));
            float n2 = tanh_f(aNX[mt][nt][2] + bnx0 + r2v * (aNH[mt][nt][2] + bnh0));
            float n3 = tanh_f(aNX[mt][nt][3] + bnx1 + r3v * (aNH[mt][nt][3] + bnh1));
            float2 o0, o1;
            o0.x = fmaf(z0, ho0.x - n0, n0);
            o0.y = fmaf(z1, ho0.y - n1, n1);
            o1.x = fmaf(z2, ho1.x - n2, n2);
            o1.y = fmaf(z3, ho1.y - n3, n3);
            sts2(h0a, o0);
            sts2(h1a, o1);
            uint32_t offh = ((uint32_t)(mt * 16 + g) * APADH + col) * 2;
            sts1u(rhOut + offh, f16x2(o0.x, o0.y));
            sts1u(rhOut + offh + 8 * APADH * 2, f16x2(o1.x, o1.y));
        }
    __syncthreads();    // rhOut complete before next consumer
}

// ================= fp16-mma 128x128 dense, SMEM(fp16)->SMEM(fp16) =================
__device__ __noinline__ void dense16(uint32_t src, uint32_t dst,
                                     const float* __restrict__ WJ,
                                     const float* __restrict__ bias, int relu) {
    const int tid = threadIdx.x, wid = tid >> 5, lane = tid & 31;
    const int g = lane >> 2, t4 = lane & 3;
    const int f = lane >> 3, r8 = lane & 7;
    const uint32_t lmoff = (uint32_t)r8 * (APADH * 2)
                         + ((f & 1) ? 8 * APADH * 2 : 0u) + ((f >> 1) ? 16u : 0u);
    float acc[2][2][4];
    #pragma unroll
    for (int m = 0; m < 2; m++)
        #pragma unroll
        for (int n = 0; n < 2; n++)
            #pragma unroll
            for (int e = 0; e < 4; e++) acc[m][n][e] = 0.0f;

    #pragma unroll 2
    for (int kt = 0; kt < 8; kt++) {
        uint32_t A0 = src + lmoff + kt * 32;
        uint32_t a[2][4];
        LDSM4(a[0][0], a[0][1], a[0][2], a[0][3], A0);
        LDSM4(a[1][0], a[1][1], a[1][2], a[1][3], A0 + 16 * APADH * 2);
        float4 bv = *reinterpret_cast<const float4*>(WJ + (kt * 8 + wid) * 128 + lane * 4);
        MMA16(acc[0][0], a[0], __float_as_uint(bv.x), __float_as_uint(bv.y));
        MMA16(acc[0][1], a[0], __float_as_uint(bv.z), __float_as_uint(bv.w));
        MMA16(acc[1][0], a[1], __float_as_uint(bv.x), __float_as_uint(bv.y));
        MMA16(acc[1][1], a[1], __float_as_uint(bv.z), __float_as_uint(bv.w));
    }
    #pragma unroll
    for (int mt = 0; mt < 2; mt++)
        #pragma unroll
        for (int nt = 0; nt < 2; nt++) {
            int col = wid * 16 + nt * 8 + t4 * 2;
            float b0 = bias[col], b1 = bias[col + 1];
            float v0 = acc[mt][nt][0] + b0, v1 = acc[mt][nt][1] + b1;
            float v2 = acc[mt][nt][2] + b0, v3 = acc[mt][nt][3] + b1;
            if (relu) {
                v0 = fmaxf(v0, 0.0f); v1 = fmaxf(v1, 0.0f);
                v2 = fmaxf(v2, 0.0f); v3 = fmaxf(v3, 0.0f);
            }
            uint32_t offh = ((uint32_t)(mt * 16 + g) * APADH + col) * 2;
            sts1u(dst + offh, f16x2(v0, v1));
            sts1u(dst + offh + 8 * APADH * 2, f16x2(v2, v3));
        }
    __syncthreads();
}

// ================= fused whole-network kernel =================
__global__ void __launch_bounds__(NTHR, 2)
k_net(const float* __restrict__ x_true, float* __restrict__ out,
      const float* __restrict__ Wemb, const float* __restrict__ bemb,
      const float* __restrict__ enc_bih, const float* __restrict__ enc_bhh,
      const float* __restrict__ enc_bt, const float* __restrict__ dec_bin,
      const float* __restrict__ dec_bih, const float* __restrict__ dec_bhh,
      const float* __restrict__ Wout, const float* __restrict__ bout) {
    extern __shared__ float sm[];
    const uint32_t sb = smem_u32(sm);
    const uint32_t he0 = sb, he1 = sb + TSZ * 4, he2 = sb + 2 * TSZ * 4;
    const uint32_t h16 = sb + 3 * TSZ * 4;
    // rh[p][l] ping-pong buffers, then rxe
    const uint32_t rxe = h16 + 6 * HTSZ * 2;
    const int tid = threadIdx.x;
    const int row0 = blockIdx.x * ROWS;
    const int NFLT = 3 * TSZ + 7 * HTSZ / 2;        // total smem floats

    auto rh = [&](int p, int l) { return h16 + (uint32_t)(p * 3 + l) * (HTSZ * 2); };

    for (int i = tid; i < NFLT; i += NTHR) sm[i] = 0.0f;
    __syncthreads();

    int pb = 0;
    // ---- encoder: steps t = 1..T-2 (step 0 discarded per reference) ----
    #pragma unroll 1
    for (int t = 1; t <= NT - 2; t++) {
        #pragma unroll 1
        for (int i = tid; i < ROWS * 64; i += NTHR) {
            int r = i >> 6, c = (i & 63) * 2;
            float2 xp = *reinterpret_cast<const float2*>(
                x_true + ((size_t)(row0 + r) * NT + t) * 2);
            float v0 = fmaxf(fmaf(xp.x, Wemb[2 * c],
                                  fmaf(xp.y, Wemb[2 * c + 1], bemb[c])), 0.0f);
            float v1 = fmaxf(fmaf(xp.x, Wemb[2 * c + 2],
                                  fmaf(xp.y, Wemb[2 * c + 3], bemb[c + 1])), 0.0f);
            sts1u(rxe + ((uint32_t)r * APADH + c) * 2, f16x2(v0, v1));
        }
        __syncthreads();
        cellf(rxe,           rh(pb, 0), he0, g_wB[0], enc_bih,          enc_bhh,          rh(pb ^ 1, 0));
        cellf(rh(pb ^ 1, 0), rh(pb, 1), he1, g_wB[1], enc_bih + G3,     enc_bhh + G3,     rh(pb ^ 1, 1));
        cellf(rh(pb ^ 1, 1), rh(pb, 2), he2, g_wB[2], enc_bih + 2 * G3, enc_bhh + 2 * G3, rh(pb ^ 1, 2));
        pb ^= 1;
    }

    // rep = h_top @ enc_Wt^T + bt (fp16, no relu) -> rh(0,0) scratch
    dense16(rh(pb, 2), rh(0, 0), g_wD[0], enc_bt, 0);
    // decoder step-0 input projection: relu(rep @ Win^T + bin) -> rxe
    dense16(rh(0, 0), rxe, g_wD[1], dec_bin, 1);

    // zero he tiles (f32) + all 6 rh buffers (fp16); keep rxe
    for (int i = tid; i < 3 * TSZ + 3 * HTSZ; i += NTHR) sm[i] = 0.0f;
    __syncthreads();

    pb = 0;
    // ---- decoder: 12 steps; carry = top hidden ----
    #pragma unroll 1
    for (int i = 0; i < NT; i++) {
        if (i) dense16(rh(pb, 2), rxe, g_wD[1], dec_bin, 1);
        cellf(rxe,           rh(pb, 0), he0, g_wB[3], dec_bih,          dec_bhh,          rh(pb ^ 1, 0));
        cellf(rh(pb ^ 1, 0), rh(pb, 1), he1, g_wB[4], dec_bih + G3,     dec_bhh + G3,     rh(pb ^ 1, 1));
        cellf(rh(pb ^ 1, 1), rh(pb, 2), he2, g_wB[5], dec_bih + 2 * G3, dec_bhh + 2 * G3, rh(pb ^ 1, 2));
        pb ^= 1;

        // output head: y = h_top @ Wout^T + bout  (exact he2; layer-2 end barrier done)
        {
            int wid = tid >> 5, lane = tid & 31;
            float4 w0 = *reinterpret_cast<const float4*>(Wout + lane * 4);
            float4 w1 = *reinterpret_cast<const float4*>(Wout + HD + lane * 4);
            #pragma unroll
            for (int rr = 0; rr < 4; rr++) {
                int r = wid * 4 + rr;
                float4 hv = *reinterpret_cast<const float4*>(
                    sm + 2 * TSZ + r * APAD + lane * 4);
                float d0 = hv.x * w0.x + hv.y * w0.y + hv.z * w0.z + hv.w * w0.w;
                float d1 = hv.x * w1.x + hv.y * w1.y + hv.z * w1.z + hv.w * w1.w;
                #pragma unroll
                for (int s = 16; s; s >>= 1) {
                    d0 += __shfl_xor_sync(0xFFFFFFFFu, d0, s);
                    d1 += __shfl_xor_sync(0xFFFFFFFFu, d1, s);
                }
                if (lane == 0) {
                    float* o = out + ((size_t)(row0 + r) * NT + i) * 2;
                    o[0] = d0 + bout[0];
                    o[1] = d1 + bout[1];
                }
            }
        }
    }
}

extern "C" void kernel_launch(void* const* d_in, const int* in_sizes, int n_in,
                              void* d_out, int out_size) {
    const float* x_true   = (const float*)d_in[0];
    const float* enc_Wemb = (const float*)d_in[1];
    const float* enc_bemb = (const float*)d_in[2];
    const float* enc_Wih  = (const float*)d_in[3];
    const float* enc_Whh  = (const float*)d_in[4];
    const float* enc_bih  = (const float*)d_in[5];
    const float* enc_bhh  = (const float*)d_in[6];
    const float* enc_Wt   = (const float*)d_in[7];
    const float* enc_bt   = (const float*)d_in[8];
    const float* dec_Win  = (const float*)d_in[9];
    const float* dec_bin  = (const float*)d_in[10];
    const float* dec_Wih  = (const float*)d_in[11];
    const float* dec_Whh  = (const float*)d_in[12];
    const float* dec_bih  = (const float*)d_in[13];
    const float* dec_bhh  = (const float*)d_in[14];
    const float* dec_Wout = (const float*)d_in[15];
    const float* dec_bout = (const float*)d_in[16];
    float* out = (float*)d_out;

    cudaFuncSetAttribute(k_net, cudaFuncAttributeMaxDynamicSharedMemorySize, SMEM_NET);

    k_prep_all<<<6 * 192, 256>>>(enc_Wih, enc_Whh, dec_Wih, dec_Whh);
    k_prep_dense<<<64, 256>>>(enc_Wt, dec_Win);
    k_net<<<NB / ROWS, NTHR, SMEM_NET>>>(x_true, out, enc_Wemb, enc_bemb,
                                         enc_bih, enc_bhh, enc_bt, dec_bin,
                                         dec_bih, dec_bhh, dec_Wout, dec_bout);
}